// round 7
// baseline (speedup 1.0000x reference)
#include <cuda_runtime.h>
#include <math.h>

#define BATCH 8
#define NPTS  8192
#define NSLOT 16                     // 8 batches x 2 clouds
#define TOTPTS (NSLOT * NPTS)        // 131072
#define G 32
#define NC (G * G * G)               // 32768 cells per grid
#define NCT (NSLOT * NC)             // 524288 cells total
#define NTILE 512                    // scan tiles (1024 cells each)
#define NCHUNK 4096                  // query warp-chunks (32 queries each)
#define LOB  (-5.5f)
#define HCELL (11.0f / G)
#define INVH  (G / 11.0f)
#define EPSF 1e-10f

#define FLG_AGG 0x40000000u
#define FLG_INC 0x80000000u
#define VALMASK 0x3FFFFFFFu

// ---- static scratch (no allocation; zero-initialized at module load) ------
__device__ float4   g_pk[TOTPTS];      // packed points, original order
__device__ float4   g_sorted[TOTPTS];  // points sorted by cell (global CSR)
__device__ int      g_cell[TOTPTS];    // flat cell id per point
__device__ int      g_cnt[NCT];        // histogram (self-cleaned by scan)
__device__ int      g_start[NCT + 1];  // CSR starts + sentinel
__device__ int      g_cursor[NCT];     // scatter cursors
__device__ int      g_ticket;          // scan tile ticket (reset by final)
__device__ unsigned g_tstate[NTILE];   // lookback states (reset by final)
__device__ float    g_wpart[NCHUNK];   // per-warp-chunk partial sums

// ---------------------------------------------------------------------------
// Pack points, compute cells, histogram.
// t in [0,131072): slot = t>>13 (b*2 + side), i = t&8191. side0=x, side1=y.
// ---------------------------------------------------------------------------
__global__ void assign_kernel(const float* __restrict__ x,
                              const float* __restrict__ y) {
    int t = blockIdx.x * 256 + threadIdx.x;
    int slot = t >> 13, i = t & (NPTS - 1);
    int b = slot >> 1;
    const float* src = (slot & 1) ? y : x;
    const float* p = src + ((size_t)b * NPTS + i) * 3;
    float px = p[0], py = p[1], pz = p[2];
    int cx = min(G - 1, max(0, (int)((px - LOB) * INVH)));
    int cy = min(G - 1, max(0, (int)((py - LOB) * INVH)));
    int cz = min(G - 1, max(0, (int)((pz - LOB) * INVH)));
    int c = slot * NC + ((cz * G + cy) * G + cx);
    g_pk[t] = make_float4(px, py, pz, 0.0f);
    g_cell[t] = c;
    atomicAdd(&g_cnt[c], 1);
}

// ---------------------------------------------------------------------------
// Single-pass exclusive scan of g_cnt (decoupled lookback, ticket-ordered
// tiles => no deadlock; output deterministic). Also zeroes g_cnt for the
// next graph replay and fills g_cursor.
// ---------------------------------------------------------------------------
__global__ void __launch_bounds__(1024) scan_kernel() {
    __shared__ int tile_s, exc_s;
    __shared__ int ws[32];
    int tid = threadIdx.x, lane = tid & 31, w = tid >> 5;

    if (tid == 0) tile_s = atomicAdd(&g_ticket, 1);
    __syncthreads();
    const int tile = tile_s;
    const int i = tile * 1024 + tid;

    int v = g_cnt[i];
    g_cnt[i] = 0;                                  // self-clean for next call

    int s = v;                                     // warp inclusive scan
    #pragma unroll
    for (int o = 1; o < 32; o <<= 1) {
        int t = __shfl_up_sync(0xffffffffu, s, o);
        if (lane >= o) s += t;
    }
    if (lane == 31) ws[w] = s;
    __syncthreads();
    if (w == 0) {
        int t = ws[lane];
        #pragma unroll
        for (int o = 1; o < 32; o <<= 1) {
            int u = __shfl_up_sync(0xffffffffu, t, o);
            if (lane >= o) t += u;
        }
        ws[lane] = t;
    }
    __syncthreads();
    int local_exc = ((w > 0) ? ws[w - 1] : 0) + s - v;
    int total = ws[31];

    if (tid == 0) {
        if (tile == 0) {
            __threadfence();
            atomicExch(&g_tstate[0], FLG_INC | (unsigned)total);
            exc_s = 0;
        } else {
            __threadfence();
            atomicExch(&g_tstate[tile], FLG_AGG | (unsigned)total);
            int exc = 0, j = tile - 1;
            while (true) {
                unsigned st = atomicAdd(&g_tstate[j], 0u);
                if (st & FLG_INC) { exc += (int)(st & VALMASK); break; }
                if (st & FLG_AGG) { exc += (int)(st & VALMASK); j--; }
            }
            __threadfence();
            atomicExch(&g_tstate[tile], FLG_INC | (unsigned)(exc + total));
            exc_s = exc;
        }
    }
    __syncthreads();
    int e = exc_s + local_exc;
    g_start[i]  = e;
    g_cursor[i] = e;
    if (i == 0) g_start[NCT] = TOTPTS;             // sentinel
}

__global__ void scatter_kernel() {
    int t = blockIdx.x * 256 + threadIdx.x;
    int pos = atomicAdd(&g_cursor[g_cell[t]], 1);
    g_sorted[pos] = g_pk[t];
}

// ---------------------------------------------------------------------------
__device__ __forceinline__ void scan_cells(int c0, int width, float4 qp,
                                           float& best) {
    int s = g_start[c0];
    int e = g_start[c0 + width];
    for (int j = s; j < e; j++) {
        float4 p = g_sorted[j];
        float dx = qp.x - p.x, dy = qp.y - p.y, dz = qp.z - p.z;
        float d2 = fmaf(dx, dx, fmaf(dy, dy, dz * dz));
        best = fminf(best, d2);
    }
}

// Exact NN via expanding Chebyshev shells over the CSR grid.
// Queries taken in CELL-SORTED order (warp lanes spatially adjacent), with a
// warp-chunk permutation c=(g*2053)&4095 to spread dense-center chunks
// uniformly across blocks (load balance). Sum of sqrt(min) is
// order-independent so the permutation does not change the result.
// Correctness: after ball r is scanned, any unscanned point is >= r*HCELL
// away (per-axis clamped cell assignment is 1-Lipschitz); stop when
// best <= (r*h)^2; worst case r reaches G => full scan => exact.
__global__ void __launch_bounds__(256) query_kernel() {
    int gwarp = blockIdx.x * 8 + (threadIdx.x >> 5);   // [0, 4096)
    int lane = threadIdx.x & 31;
    int c = (gwarp * 2053) & (NCHUNK - 1);             // permuted chunk
    int qid = c * 32 + lane;                           // [0, 131072)
    int d = qid >> 16;                                 // direction
    int q = qid & 65535;
    int b = q >> 13;                                   // batch
    int i = q & (NPTS - 1);                            // sorted index in slot
    int qslot  = b * 2 + d;
    int dbslot = b * 2 + (1 - d);

    float4 qp = g_sorted[qslot * NPTS + i];            // cell-sorted query
    int cx = min(G - 1, max(0, (int)((qp.x - LOB) * INVH)));
    int cy = min(G - 1, max(0, (int)((qp.y - LOB) * INVH)));
    int cz = min(G - 1, max(0, (int)((qp.z - LOB) * INVH)));
    const int base = dbslot * NC;

    float best = 1e30f;

    // Ball r=1 (27 cells as 9 contiguous x-rows)
    for (int dz = -1; dz <= 1; dz++) {
        int z = cz + dz;
        if ((unsigned)z >= G) continue;
        for (int dy = -1; dy <= 1; dy++) {
            int y = cy + dy;
            if ((unsigned)y >= G) continue;
            int x0 = max(cx - 1, 0), x1 = min(cx + 1, G - 1);
            scan_cells(base + (z * G + y) * G + x0, x1 - x0 + 1, qp, best);
        }
    }

    int r = 1;
    while (!(best <= (r * HCELL) * (r * HCELL) * 0.9999f) && r < G) {
        r++;
        for (int dz = -r; dz <= r; dz++) {             // shell at dist r
            int z = cz + dz;
            if ((unsigned)z >= G) continue;
            int adz = (dz < 0) ? -dz : dz;
            for (int dy = -r; dy <= r; dy++) {
                int y = cy + dy;
                if ((unsigned)y >= G) continue;
                int ady = (dy < 0) ? -dy : dy;
                int rowbase = base + (z * G + y) * G;
                if (adz == r || ady == r) {
                    int x0 = max(cx - r, 0), x1 = min(cx + r, G - 1);
                    scan_cells(rowbase + x0, x1 - x0 + 1, qp, best);
                } else {
                    int xa = cx - r;
                    if (xa >= 0) scan_cells(rowbase + xa, 1, qp, best);
                    int xb = cx + r;
                    if (xb < G) scan_cells(rowbase + xb, 1, qp, best);
                }
            }
        }
    }

    float dist = sqrtf(best + EPSF);
    #pragma unroll
    for (int o = 16; o > 0; o >>= 1)
        dist += __shfl_down_sync(0xffffffffu, dist, o);
    if (lane == 0) g_wpart[c] = dist;
}

// ---------------------------------------------------------------------------
// Fold 4096 chunk-partials -> 16 (d,b) sums -> max over d -> mean -> total.
// Chunk c: d = c>>11, b = (c>>8)&7  => group = c>>8. Also resets scan state
// (g_tstate, g_ticket) for the next graph replay.
// ---------------------------------------------------------------------------
__global__ void __launch_bounds__(512) final_kernel(float* __restrict__ out) {
    int t = threadIdx.x, grp = t >> 5, lane = t & 31;
    g_tstate[t] = 0u;                              // scan-state cleanup
    if (t == 0) g_ticket = 0;

    float s = 0.0f;
    #pragma unroll
    for (int k = 0; k < 8; k++)
        s += g_wpart[grp * 256 + k * 32 + lane];
    #pragma unroll
    for (int o = 16; o > 0; o >>= 1)
        s += __shfl_down_sync(0xffffffffu, s, o);

    __shared__ float ss[16];
    if (lane == 0) ss[grp] = s;
    __syncthreads();
    if (t == 0) {
        float tot = 0.0f;
        #pragma unroll
        for (int bb = 0; bb < BATCH; bb++)
            tot += fmaxf(ss[bb], ss[8 + bb]) * (1.0f / NPTS);
        out[0] = tot;
    }
}

// ---------------------------------------------------------------------------
extern "C" void kernel_launch(void* const* d_in, const int* in_sizes, int n_in,
                              void* d_out, int out_size) {
    const float* x = (const float*)d_in[0];
    const float* y = (const float*)d_in[1];
    float* out = (float*)d_out;

    assign_kernel<<<TOTPTS / 256, 256>>>(x, y);
    scan_kernel<<<NTILE, 1024>>>();
    scatter_kernel<<<TOTPTS / 256, 256>>>();
    query_kernel<<<512, 256>>>();
    final_kernel<<<1, 512>>>(out);
}